// round 3
// baseline (speedup 1.0000x reference)
#include <cuda_runtime.h>
#include <cstdint>

// Problem constants
constexpr int NN  = 8192;  // nodes (M and K of each GEMM)
constexpr int WID = 128;   // D + E
constexpr int DCOL = 64;   // relu applied to cols < DCOL

// Scratch (no cudaMalloc allowed): packed input features and layer-1 output
__device__ float g_W [NN * WID];
__device__ float g_X1[NN * WID];

// ---------------------------------------------------------------------------
// Pack W = [F | new_features]  (both [NN, 64])
// ---------------------------------------------------------------------------
__global__ void pack_kernel(const float* __restrict__ F,
                            const float* __restrict__ NF) {
    int i = blockIdx.x * blockDim.x + threadIdx.x;   // over NN*64
    if (i < NN * DCOL) {
        int r = i >> 6;
        int c = i & 63;
        g_W[r * WID + c]        = F[i];
        g_W[r * WID + DCOL + c] = NF[i];
    }
}

// ---------------------------------------------------------------------------
// Packed f32x2 helpers (Blackwell FFMA2 path — only reachable via PTX)
// ---------------------------------------------------------------------------
typedef unsigned long long u64;

__device__ __forceinline__ u64 dup2(float x) {
    u64 r;
    unsigned int u = __float_as_uint(x);
    asm("mov.b64 %0, {%1, %1};" : "=l"(r) : "r"(u));
    return r;
}

__device__ __forceinline__ void fma2(u64& d, u64 a, u64 b) {
    asm("fma.rn.f32x2 %0, %1, %2, %0;" : "+l"(d) : "l"(a), "l"(b));
}

__device__ __forceinline__ void unpack2(u64 v, float& lo, float& hi) {
    unsigned int l, h;
    asm("mov.b64 {%0, %1}, %2;" : "=r"(l), "=r"(h) : "l"(v));
    lo = __uint_as_float(l);
    hi = __uint_as_float(h);
}

// ---------------------------------------------------------------------------
// C[NN, WID] = epilogue( A[NN, NN] @ B[NN, WID] )
// epilogue: relu on columns < DCOL (same for both layers)
// FIRST = true : B = g_W,  C = g_X1
// FIRST = false: B = g_X1, C = outp
//
// Tiling: BM=64, BN=128(full width), BK=16, 256 threads,
//         thread micro-tile 4(M) x 8(N) as 16 packed f32x2 accumulators.
// ---------------------------------------------------------------------------
template <bool FIRST>
__global__ __launch_bounds__(256, 1)
void gemm_layer(const float* __restrict__ A, float* __restrict__ outp) {
    constexpr int BM = 64, BN = 128, BK = 16;
    constexpr int TM = 4, TN = 8, TN2 = TN / 2;

    const float* __restrict__ B = FIRST ? g_W  : g_X1;
    float*       __restrict__ C = FIRST ? g_X1 : outp;

    __shared__ float As[2][BK][BM];   // [k][m]
    __shared__ float Bs[2][BK][BN];   // [k][n]

    const int tid = threadIdx.x;
    const int tx  = tid & 15;         // 0..15  (N direction, TN=8 each)
    const int ty  = tid >> 4;         // 0..15  (M direction, TM=4 each)
    const int block_m = blockIdx.x * BM;

    // Global-load assignments (one tile = 64x16 A floats + 16x128 B floats)
    const int a_row  = tid >> 2;            // 0..63
    const int a_col4 = (tid & 3) * 4;       // 0,4,8,12
    const int b_row  = tid >> 5;            // 0..7  (rows b_row and b_row+8)
    const int b_col4 = (tid & 31) * 4;      // 0..124

    const float* a_src = &A[(block_m + a_row) * NN + a_col4];

    u64 acc[TM][TN2];
    #pragma unroll
    for (int i = 0; i < TM; ++i)
        #pragma unroll
        for (int j = 0; j < TN2; ++j) acc[i][j] = 0ull;

    // ---- preload tile 0 into buffer 0 ----
    {
        float4 pa  = *reinterpret_cast<const float4*>(a_src);
        float4 pb0 = *reinterpret_cast<const float4*>(&B[(b_row)     * WID + b_col4]);
        float4 pb1 = *reinterpret_cast<const float4*>(&B[(b_row + 8) * WID + b_col4]);
        As[0][a_col4 + 0][a_row] = pa.x;
        As[0][a_col4 + 1][a_row] = pa.y;
        As[0][a_col4 + 2][a_row] = pa.z;
        As[0][a_col4 + 3][a_row] = pa.w;
        *reinterpret_cast<float4*>(&Bs[0][b_row][b_col4])     = pb0;
        *reinterpret_cast<float4*>(&Bs[0][b_row + 8][b_col4]) = pb1;
    }
    __syncthreads();

    const int ntiles = NN / BK;   // 512

    // ---- main loop: iterations 0 .. ntiles-2 each prefetch the next tile ----
    for (int t = 0; t < ntiles - 1; ++t) {
        const int cur = t & 1;
        const int kt  = (t + 1) * BK;

        // stage next tile's global loads into registers
        float4 pa  = *reinterpret_cast<const float4*>(a_src + kt);
        float4 pb0 = *reinterpret_cast<const float4*>(&B[(kt + b_row)     * WID + b_col4]);
        float4 pb1 = *reinterpret_cast<const float4*>(&B[(kt + b_row + 8) * WID + b_col4]);

        // ---- compute on current buffer ----
        #pragma unroll
        for (int k = 0; k < BK; ++k) {
            float4 af = *reinterpret_cast<const float4*>(&As[cur][k][ty * TM]);
            u64 a2[TM] = { dup2(af.x), dup2(af.y), dup2(af.z), dup2(af.w) };

            ulonglong2 bq0 = *reinterpret_cast<const ulonglong2*>(&Bs[cur][k][tx * TN]);
            ulonglong2 bq1 = *reinterpret_cast<const ulonglong2*>(&Bs[cur][k][tx * TN + 4]);
            u64 b2[TN2] = { bq0.x, bq0.y, bq1.x, bq1.y };

            #pragma unroll
            for (int i = 0; i < TM; ++i)
                #pragma unroll
                for (int j = 0; j < TN2; ++j)
                    fma2(acc[i][j], a2[i], b2[j]);
        }

        // ---- commit staged tile to the other buffer ----
        const int nb = cur ^ 1;
        As[nb][a_col4 + 0][a_row] = pa.x;
        As[nb][a_col4 + 1][a_row] = pa.y;
        As[nb][a_col4 + 2][a_row] = pa.z;
        As[nb][a_col4 + 3][a_row] = pa.w;
        *reinterpret_cast<float4*>(&Bs[nb][b_row][b_col4])     = pb0;
        *reinterpret_cast<float4*>(&Bs[nb][b_row + 8][b_col4]) = pb1;
        __syncthreads();
    }

    // ---- final tile (no prefetch) ----
    {
        const int cur = (ntiles - 1) & 1;
        #pragma unroll
        for (int k = 0; k < BK; ++k) {
            float4 af = *reinterpret_cast<const float4*>(&As[cur][k][ty * TM]);
            u64 a2[TM] = { dup2(af.x), dup2(af.y), dup2(af.z), dup2(af.w) };

            ulonglong2 bq0 = *reinterpret_cast<const ulonglong2*>(&Bs[cur][k][tx * TN]);
            ulonglong2 bq1 = *reinterpret_cast<const ulonglong2*>(&Bs[cur][k][tx * TN + 4]);
            u64 b2[TN2] = { bq0.x, bq0.y, bq1.x, bq1.y };

            #pragma unroll
            for (int i = 0; i < TM; ++i)
                #pragma unroll
                for (int j = 0; j < TN2; ++j)
                    fma2(acc[i][j], a2[i], b2[j]);
        }
    }

    // ---- epilogue: relu on cols < DCOL, vectorized stores ----
    const bool do_relu = (tx * TN) < DCOL;   // each thread's 8 cols are on one side
    #pragma unroll
    for (int i = 0; i < TM; ++i) {
        const int row = block_m + ty * TM + i;
        float v[TN];
        #pragma unroll
        for (int j = 0; j < TN2; ++j) unpack2(acc[i][j], v[2 * j], v[2 * j + 1]);
        if (do_relu) {
            #pragma unroll
            for (int j = 0; j < TN; ++j) v[j] = fmaxf(v[j], 0.0f);
        }
        float4* cp = reinterpret_cast<float4*>(&C[row * WID + tx * TN]);
        cp[0] = make_float4(v[0], v[1], v[2], v[3]);
        cp[1] = make_float4(v[4], v[5], v[6], v[7]);
    }
}

// ---------------------------------------------------------------------------
// Launch: pack -> layer1 (W -> X1) -> layer2 (X1 -> out)
// All plain kernel launches: graph-capturable, allocation-free.
// ---------------------------------------------------------------------------
extern "C" void kernel_launch(void* const* d_in, const int* in_sizes, int n_in,
                              void* d_out, int out_size) {
    const float* A  = (const float*)d_in[0];
    const float* F  = (const float*)d_in[1];
    const float* NF = (const float*)d_in[2];
    float* out = (float*)d_out;

    pack_kernel<<<(NN * DCOL + 255) / 256, 256>>>(F, NF);
    gemm_layer<true ><<<NN / 64, 256>>>(A, out);   // W  -> X1
    gemm_layer<false><<<NN / 64, 256>>>(A, out);   // X1 -> out
}

// round 7
// speedup vs baseline: 3.4326x; 3.4326x over previous
#include <cuda_runtime.h>
#include <cuda_bf16.h>
#include <cstdint>

// ---------------------------------------------------------------------------
// out = concat( relu(A@relu(A@F)), A@(A@NF) ), N=8192, D=E=64.
// Both layers: C[8192,128] = A[8192,8192] @ W[8192,128], relu on cols<64.
// Path: mma.sync HMMA bf16 (sm_103-safe; tcgen05 needs the 'a' target the
// harness PTX doesn't request), 3-term hi/lo split, fp32 accum.
// ---------------------------------------------------------------------------

constexpr int NN  = 8192;
constexpr int WID = 128;

// smem tile layout (bf16, K-contiguous rows padded to 80B => conflict-free
// ldmatrix: bank stride 20 per row)
constexpr int PITCH_B = 80;                 // bytes per 32-element bf16 row
constexpr int AH_OFF = 0;                   // A_hi: 64 rows  -> 5120 B
constexpr int AL_OFF = 5120;                // A_lo: 64 rows
constexpr int BH_OFF = 10240;               // B_hi: 128 rows -> 10240 B
constexpr int BL_OFF = 20480;               // B_lo: 128 rows
constexpr int BUF_BYTES  = 30720;           // one stage
constexpr int SMEM_GEMM  = 2 * BUF_BYTES;   // 61440 (also covers 34816B epilogue)

// B operands stored [n][k] (k contiguous) == col-major for mma "col" B.
__device__ __align__(16) __nv_bfloat16 g_B1h[(size_t)WID * NN];
__device__ __align__(16) __nv_bfloat16 g_B1l[(size_t)WID * NN];
__device__ __align__(16) __nv_bfloat16 g_B2h[(size_t)WID * NN];
__device__ __align__(16) __nv_bfloat16 g_B2l[(size_t)WID * NN];

// ---------------------------------------------------------------------------
// helpers
// ---------------------------------------------------------------------------
__device__ __forceinline__ uint32_t s2u(const void* p) {
    uint32_t a;
    asm("{ .reg .u64 t; cvta.to.shared.u64 t, %1; cvt.u32.u64 %0, t; }"
        : "=r"(a) : "l"(p));
    return a;
}

__device__ __forceinline__ void ldmx4(uint32_t* r, uint32_t addr) {
    asm volatile("ldmatrix.sync.aligned.m8n8.x4.shared.b16 {%0,%1,%2,%3}, [%4];"
                 : "=r"(r[0]), "=r"(r[1]), "=r"(r[2]), "=r"(r[3]) : "r"(addr));
}

__device__ __forceinline__ void mma16816(float* c, const uint32_t* a,
                                         const uint32_t* b) {
    asm volatile(
        "mma.sync.aligned.m16n8k16.row.col.f32.bf16.bf16.f32 "
        "{%0,%1,%2,%3}, {%4,%5,%6,%7}, {%8,%9}, {%0,%1,%2,%3};"
        : "+f"(c[0]), "+f"(c[1]), "+f"(c[2]), "+f"(c[3])
        : "r"(a[0]), "r"(a[1]), "r"(a[2]), "r"(a[3]), "r"(b[0]), "r"(b[1]));
}

__device__ __forceinline__ uint32_t packbf(float lo_elem, float hi_elem) {
    __nv_bfloat162 t = __halves2bfloat162(__float2bfloat16_rn(lo_elem),
                                          __float2bfloat16_rn(hi_elem));
    return *reinterpret_cast<uint32_t*>(&t);
}

// split 8 fp32 -> 8 bf16 hi + 8 bf16 lo
__device__ __forceinline__ void split8(float4 x, float4 y, uint4& h, uint4& l) {
    float v[8] = {x.x, x.y, x.z, x.w, y.x, y.y, y.z, y.w};
    uint32_t hw[4], lw[4];
    #pragma unroll
    for (int i = 0; i < 4; ++i) {
        float a = v[2 * i], b = v[2 * i + 1];
        __nv_bfloat16 ha = __float2bfloat16_rn(a);
        __nv_bfloat16 hb = __float2bfloat16_rn(b);
        hw[i] = packbf(a, b);                 // rounded inside
        lw[i] = packbf(a - __bfloat162float(ha), b - __bfloat162float(hb));
    }
    h = make_uint4(hw[0], hw[1], hw[2], hw[3]);
    l = make_uint4(lw[0], lw[1], lw[2], lw[3]);
}

// ---------------------------------------------------------------------------
// conv_b1: transpose+split W=[F|NF] -> B1 [n][k] bf16 hi/lo
// ---------------------------------------------------------------------------
__global__ void conv_b1(const float* __restrict__ F, const float* __restrict__ NF) {
    __shared__ float tile[32][33];
    int k0 = blockIdx.x * 32, n0 = blockIdx.y * 32;
    int tx = threadIdx.x, ty = threadIdx.y;             // (32, 8)
    const float* src = (n0 < 64) ? F : NF;
    int nc = (n0 < 64) ? n0 : (n0 - 64);
    #pragma unroll
    for (int j = 0; j < 4; ++j) {
        int r = ty + 8 * j;
        tile[r][tx] = src[(size_t)(k0 + r) * 64 + nc + tx];
    }
    __syncthreads();
    #pragma unroll
    for (int j = 0; j < 4; ++j) {
        int rn = ty + 8 * j;
        float v = tile[tx][rn];                          // W[k0+tx][n0+rn]
        __nv_bfloat16 h = __float2bfloat16_rn(v);
        __nv_bfloat16 l = __float2bfloat16_rn(v - __bfloat162float(h));
        size_t o = (size_t)(n0 + rn) * NN + k0 + tx;
        g_B1h[o] = h;
        g_B1l[o] = l;
    }
}

// ---------------------------------------------------------------------------
// GEMM tile compute: one BK=32 chunk, 3 terms, warp tile 32x32
// ---------------------------------------------------------------------------
__device__ __forceinline__ void compute_tile(uint32_t base, uint32_t aLaneOff,
                                             uint32_t bLaneOff, int warp_m,
                                             int warp_n, float (&acc)[2][4][4]) {
    const uint32_t aoff = base + warp_m * 2560 + aLaneOff;          // AH region
    const uint32_t boff = base + BH_OFF + warp_n * 2560 + bLaneOff; // BH region
    #pragma unroll
    for (int ks = 0; ks < 2; ++ks) {
        uint32_t ah[2][4], al[2][4], bh[2][4], bl[2][4];
        ldmx4(ah[0], aoff + ks * 32);
        ldmx4(ah[1], aoff + ks * 32 + 1280);
        ldmx4(al[0], aoff + ks * 32 + AL_OFF);
        ldmx4(al[1], aoff + ks * 32 + AL_OFF + 1280);
        ldmx4(bh[0], boff + ks * 32);
        ldmx4(bh[1], boff + ks * 32 + 1280);
        ldmx4(bl[0], boff + ks * 32 + 10240);
        ldmx4(bl[1], boff + ks * 32 + 10240 + 1280);
        #pragma unroll
        for (int mt = 0; mt < 2; ++mt)
            #pragma unroll
            for (int nt = 0; nt < 4; ++nt) {
                const uint32_t* b2h = &bh[nt >> 1][(nt & 1) * 2];
                const uint32_t* b2l = &bl[nt >> 1][(nt & 1) * 2];
                mma16816(acc[mt][nt], ah[mt], b2h);
                mma16816(acc[mt][nt], al[mt], b2h);
                mma16816(acc[mt][nt], ah[mt], b2l);
            }
    }
}

// ---------------------------------------------------------------------------
// gemm_hmma<LAYER>: C = A @ W.  A fp32 from gmem, split to bf16 in-kernel.
// LAYER==1: B=B1, epilogue -> g_B2 (transposed, bf16 hi/lo, relu cols<64)
// LAYER==2: B=B2, epilogue -> out fp32 (relu cols<64)
// ---------------------------------------------------------------------------
template <int LAYER>
__global__ __launch_bounds__(256, 1)
void gemm_hmma(const float* __restrict__ A, float* __restrict__ outp) {
    extern __shared__ char smem[];
    const uint32_t sb = s2u(smem);
    const int tid = threadIdx.x, lane = tid & 31, wid = tid >> 5;
    const int warp_m = wid >> 2, warp_n = wid & 3;
    const int m0 = blockIdx.x * 64;

    const __nv_bfloat16* __restrict__ Bh = (LAYER == 1) ? g_B1h : g_B2h;
    const __nv_bfloat16* __restrict__ Bl = (LAYER == 1) ? g_B1l : g_B2l;

    // ldmatrix lane offsets (A: row=lane%16, col16B=lane/16; B: x4 over 16 n)
    const uint32_t aLaneOff = (lane & 15) * PITCH_B + (lane >> 4) * 16;
    const uint32_t n_in16   = (lane & 7) + ((lane >> 4) << 3);
    const uint32_t bLaneOff = n_in16 * PITCH_B + ((lane >> 3) & 1) * 16;

    // global/staging assignments
    const int arow = tid >> 2, ac = (tid & 3) * 8;
    const float* gA = A + (size_t)(m0 + arow) * NN + ac;       // 8 fp32 per thread
    const __nv_bfloat16* gBh0 = Bh + (size_t)arow * NN + ac;
    const __nv_bfloat16* gBh1 = Bh + (size_t)(64 + arow) * NN + ac;
    const __nv_bfloat16* gBl0 = Bl + (size_t)arow * NN + ac;
    const __nv_bfloat16* gBl1 = Bl + (size_t)(64 + arow) * NN + ac;
    const uint32_t sAoff = arow * PITCH_B + (tid & 3) * 16;
    const uint32_t sBoff = sAoff;                              // rows 0-63
    char* sm = smem;

    float acc[2][4][4];
    #pragma unroll
    for (int i = 0; i < 2; ++i)
        #pragma unroll
        for (int j = 0; j < 4; ++j)
            #pragma unroll
            for (int q = 0; q < 4; ++q) acc[i][j][q] = 0.0f;

    // ---- preload tile 0 -> buffer 0 ----
    {
        float4 a0 = *reinterpret_cast<const float4*>(gA);
        float4 a1 = *reinterpret_cast<const float4*>(gA + 4);
        uint4 h, l;
        split8(a0, a1, h, l);
        *reinterpret_cast<uint4*>(sm + AH_OFF + sAoff) = h;
        *reinterpret_cast<uint4*>(sm + AL_OFF + sAoff) = l;
        *reinterpret_cast<uint4*>(sm + BH_OFF + sBoff) =
            *reinterpret_cast<const uint4*>(gBh0);
        *reinterpret_cast<uint4*>(sm + BH_OFF + 5120 + sBoff) =
            *reinterpret_cast<const uint4*>(gBh1);
        *reinterpret_cast<uint4*>(sm + BL_OFF + sBoff) =
            *reinterpret_cast<const uint4*>(gBl0);
        *reinterpret_cast<uint4*>(sm + BL_OFF + 5120 + sBoff) =
            *reinterpret_cast<const uint4*>(gBl1);
    }
    __syncthreads();

    // ---- main loop: 256 chunks of BK=32, register-staged prefetch ----
    #pragma unroll 1
    for (int t = 0; t < 255; ++t) {
        const int kc = (t + 1) * 32;
        float4 pa0 = *reinterpret_cast<const float4*>(gA + kc);
        float4 pa1 = *reinterpret_cast<const float4*>(gA + kc + 4);
        uint4 pbh0 = *reinterpret_cast<const uint4*>(gBh0 + kc);
        uint4 pbh1 = *reinterpret_cast<const uint4*>(gBh1 + kc);
        uint4 pbl0 = *reinterpret_cast<const uint4*>(gBl0 + kc);
        uint4 pbl1 = *reinterpret_cast<const uint4*>(gBl1 + kc);

        compute_tile(sb + (uint32_t)(t & 1) * BUF_BYTES, aLaneOff, bLaneOff,
                     warp_m, warp_n, acc);

        char* nb = sm + ((t + 1) & 1) * BUF_BYTES;
        uint4 h, l;
        split8(pa0, pa1, h, l);
        *reinterpret_cast<uint4*>(nb + AH_OFF + sAoff) = h;
        *reinterpret_cast<uint4*>(nb + AL_OFF + sAoff) = l;
        *reinterpret_cast<uint4*>(nb + BH_OFF + sBoff)        = pbh0;
        *reinterpret_cast<uint4*>(nb + BH_OFF + 5120 + sBoff) = pbh1;
        *reinterpret_cast<uint4*>(nb + BL_OFF + sBoff)        = pbl0;
        *reinterpret_cast<uint4*>(nb + BL_OFF + 5120 + sBoff) = pbl1;
        __syncthreads();
    }
    compute_tile(sb + (uint32_t)(255 & 1) * BUF_BYTES, aLaneOff, bLaneOff,
                 warp_m, warp_n, acc);
    __syncthreads();

    // ---- epilogue ----
    const int r_base = warp_m * 32 + (lane >> 2);
    const int c_base = warp_n * 32 + (lane & 3) * 2;

    if (LAYER == 1) {
        // stage fp32 [n][k] in smem (pitch 68 floats), then coalesced split-out
        float* sE = reinterpret_cast<float*>(smem);
        #pragma unroll
        for (int mt = 0; mt < 2; ++mt)
            #pragma unroll
            for (int nt = 0; nt < 4; ++nt) {
                int r = r_base + mt * 16;
                int c = c_base + nt * 8;
                float v0 = acc[mt][nt][0], v1 = acc[mt][nt][1];
                float v2 = acc[mt][nt][2], v3 = acc[mt][nt][3];
                if (c < 64) {                       // relu on global cols < 64
                    v0 = fmaxf(v0, 0.0f); v1 = fmaxf(v1, 0.0f);
                    v2 = fmaxf(v2, 0.0f); v3 = fmaxf(v3, 0.0f);
                }
                sE[(c    ) * 68 + r    ] = v0;
                sE[(c + 1) * 68 + r    ] = v1;
                sE[(c    ) * 68 + r + 8] = v2;
                sE[(c + 1) * 68 + r + 8] = v3;
            }
        __syncthreads();
        const int n = tid >> 1, k0 = (tid & 1) * 32;
        const float* src = sE + n * 68 + k0;
        uint32_t hw[16], lw[16];
        #pragma unroll
        for (int j = 0; j < 16; ++j) {
            float a = src[2 * j], b = src[2 * j + 1];
            __nv_bfloat16 ha = __float2bfloat16_rn(a);
            __nv_bfloat16 hb = __float2bfloat16_rn(b);
            hw[j] = packbf(a, b);
            lw[j] = packbf(a - __bfloat162float(ha), b - __bfloat162float(hb));
        }
        size_t o = (size_t)n * NN + m0 + k0;
        uint4* dh = reinterpret_cast<uint4*>(g_B2h + o);
        uint4* dl = reinterpret_cast<uint4*>(g_B2l + o);
        #pragma unroll
        for (int q = 0; q < 4; ++q) {
            dh[q] = make_uint4(hw[4 * q], hw[4 * q + 1], hw[4 * q + 2], hw[4 * q + 3]);
            dl[q] = make_uint4(lw[4 * q], lw[4 * q + 1], lw[4 * q + 2], lw[4 * q + 3]);
        }
    } else {
        #pragma unroll
        for (int mt = 0; mt < 2; ++mt)
            #pragma unroll
            for (int nt = 0; nt < 4; ++nt) {
                int r = m0 + r_base + mt * 16;
                int c = c_base + nt * 8;
                float v0 = acc[mt][nt][0], v1 = acc[mt][nt][1];
                float v2 = acc[mt][nt][2], v3 = acc[mt][nt][3];
                if (c < 64) {
                    v0 = fmaxf(v0, 0.0f); v1 = fmaxf(v1, 0.0f);
                    v2 = fmaxf(v2, 0.0f); v3 = fmaxf(v3, 0.0f);
                }
                *reinterpret_cast<float2*>(&outp[(size_t)r * WID + c]) =
                    make_float2(v0, v1);
                *reinterpret_cast<float2*>(&outp[(size_t)(r + 8) * WID + c]) =
                    make_float2(v2, v3);
            }
    }
}

// ---------------------------------------------------------------------------
// launch: conv_b1 -> layer1 -> layer2. Graph-capturable, allocation-free.
// ---------------------------------------------------------------------------
extern "C" void kernel_launch(void* const* d_in, const int* in_sizes, int n_in,
                              void* d_out, int out_size) {
    const float* A  = (const float*)d_in[0];
    const float* F  = (const float*)d_in[1];
    const float* NF = (const float*)d_in[2];
    float* out = (float*)d_out;

    cudaFuncSetAttribute(gemm_hmma<1>, cudaFuncAttributeMaxDynamicSharedMemorySize, SMEM_GEMM);
    cudaFuncSetAttribute(gemm_hmma<2>, cudaFuncAttributeMaxDynamicSharedMemorySize, SMEM_GEMM);

    conv_b1<<<dim3(NN / 32, WID / 32), dim3(32, 8)>>>(F, NF);
    gemm_hmma<1><<<NN / 64, 256, SMEM_GEMM>>>(A, nullptr);
    gemm_hmma<2><<<NN / 64, 256, SMEM_GEMM>>>(A, out);
}